// round 1
// baseline (speedup 1.0000x reference)
#include <cuda_runtime.h>
#include <math.h>

// ---------------- problem constants ----------------
#define NMAT 8193
#define NI   8192
#define KCORR 2048u
#define MAXC 8192
#define NGRID 52
#define CAP  (1u << 23)   // candidate buffer entries (8M -> 64MB)
#define CAP2 (1u << 17)   // selected buffer entries (131072)
#define MARGIN 0.005f

// ---------------- device scratch ----------------
__device__ float    g_cand_v[CAP];
__device__ int      g_cand_idx[CAP];
__device__ float    g_sel_v[CAP2];
__device__ int      g_sel_idx[CAP2];
__device__ float    g_logref[NI];
__device__ float    g_logsrc[NI];
__device__ unsigned g_cand_count;
__device__ unsigned g_sel_count;
__device__ unsigned g_c49, g_c50;
__device__ unsigned g_hist[64];
__device__ float    g_grid[NGRID];
__device__ float    g_thres;
__device__ float    g_W48m, g_W49p, g_W49m, g_W50p, g_W50m;
__device__ int      g_t50pos;
__device__ int      g_need_hist_full;
__device__ int      g_need_select_full;

// ---------------- prep: logs, grid, resets ----------------
__global__ void k_prep(const float* __restrict__ refw, const float* __restrict__ srcw) {
    int gid = blockIdx.x * blockDim.x + threadIdx.x;
    if (gid < NI) {
        g_logref[gid] = logf(refw[gid]);
        g_logsrc[gid] = logf(srcw[gid]);
    }
    if (gid < 64) g_hist[gid] = 0;
    if (gid == 0) {
        g_cand_count = 0; g_sel_count = 0; g_c49 = 0; g_c50 = 0;
        g_need_hist_full = 0; g_need_select_full = 0;
        float t = 0.5f;
        for (int k = 0; k < NGRID; k++) { g_grid[k] = t; t -= 0.01f; }
        float t48 = g_grid[48], t49 = g_grid[49], t50 = g_grid[50];
        g_W48m = logf(t48) - MARGIN;
        g_W49p = logf(t49) + MARGIN;
        g_W49m = logf(t49) - MARGIN;
        if (t50 > 0.0f) {
            g_t50pos = 1;
            g_W50p = logf(t50) + MARGIN;
            g_W50m = logf(t50) - MARGIN;
        } else {
            g_t50pos = 0; g_W50p = 0.0f; g_W50m = 0.0f;
        }
    }
}

// ---------------- main pass: log-domain filter + candidate capture ----------------
// grid = 16384 blocks (2 per row), 256 threads, 4096 elems/block
__global__ __launch_bounds__(256) void k_pass1(const float* __restrict__ sc) {
    __shared__ float    sv[4096];
    __shared__ int      si[4096];
    __shared__ unsigned s_cnt, s_base;
    if (threadIdx.x == 0) s_cnt = 0;
    __syncthreads();

    int row   = blockIdx.x >> 1;
    int jbase = (blockIdx.x & 1) << 12;
    const float* rp  = sc + (size_t)row * NMAT + jbase;
    const float* lsp = g_logsrc + jbase;
    float lr   = g_logref[row];
    float wlim = g_W48m;
    unsigned lane = threadIdx.x & 31u;

#pragma unroll
    for (int k = 0; k < 16; k++) {
        int   jo = threadIdx.x + (k << 8);
        float s  = rp[jo];
        float w  = s + (lr + lsp[jo]);
        bool pred = (w > wlim);
        unsigned m = __ballot_sync(0xffffffffu, pred);
        if (m) {
            unsigned base;
            int leader = __ffs(m) - 1;
            if ((int)lane == leader) base = atomicAdd(&s_cnt, (unsigned)__popc(m));
            base = __shfl_sync(0xffffffffu, base, leader);
            if (pred) {
                unsigned slot = base + __popc(m & ((1u << lane) - 1u));
                sv[slot] = s;                         // store raw score, exp later
                si[slot] = (row << 13) | (jbase + jo);
            }
        }
    }
    __syncthreads();
    unsigned n = s_cnt;
    if (threadIdx.x == 0 && n) s_base = atomicAdd(&g_cand_count, n);
    __syncthreads();
    if (!n) return;
    unsigned gb = s_base;
    // compute exact v for candidates here (sparse -> cheap MUFU), flush coalesced
    const float* srcw_row = lsp; (void)srcw_row;
    for (unsigned i = threadIdx.x; i < n; i += 256) {
        unsigned slot = gb + i;
        if (slot < CAP) {
            int   idx = si[i];
            int   j   = idx & 8191;
            float s   = sv[i];
            // recompute exact reference value: expf(s) * (ref[row]*src[j])
            float v = expf(s) * (__expf(0.0f) == 1.0f ? 1.0f : 1.0f); // placeholder avoided below
            (void)v;
            g_cand_idx[slot] = idx;
            g_cand_v[slot]   = s;   // temporarily store s; finalized in k_finalize
            (void)j;
        }
    }
}

// finalize candidate values exactly as the reference computes them:
// v = expf(s) * (ref[i] * src[j])
__global__ void k_finalize(const float* __restrict__ refw, const float* __restrict__ srcw) {
    unsigned n = g_cand_count; if (n > CAP) n = CAP;
    unsigned T = gridDim.x * blockDim.x;
    for (unsigned i = blockIdx.x * blockDim.x + threadIdx.x; i < n; i += T) {
        int idx = g_cand_idx[i];
        int r = idx >> 13, c = idx & 8191;
        float s = g_cand_v[i];
        g_cand_v[i] = expf(s) * (refw[r] * srcw[c]);
    }
}

// ---------------- histogram candidates over grid buckets 0..48 ----------------
__global__ void k_hist() {
    __shared__ unsigned h[49];
    __shared__ float    gs[49];
    if (threadIdx.x < 49) { h[threadIdx.x] = 0; gs[threadIdx.x] = g_grid[threadIdx.x]; }
    __syncthreads();
    unsigned n = g_cand_count; if (n > CAP) n = CAP;
    float t48 = gs[48];
    unsigned T = gridDim.x * blockDim.x;
    for (unsigned i = blockIdx.x * blockDim.x + threadIdx.x; i < n; i += T) {
        float v = g_cand_v[i];
        if (v > t48) {
            int lo = 0, hi = 48;
            while (lo < hi) { int mid = (lo + hi) >> 1; if (gs[mid] < v) hi = mid; else lo = mid + 1; }
            atomicAdd(&h[lo], 1u);
        }
    }
    __syncthreads();
    if (threadIdx.x < 49 && h[threadIdx.x]) atomicAdd(&g_hist[threadIdx.x], h[threadIdx.x]);
}

// ---------------- find threshold (primary) ----------------
__global__ void k_thres() {
    if (blockIdx.x | threadIdx.x) return;
    unsigned cc = g_cand_count;
    bool ovf = (cc > CAP);
    int kstar = -1; unsigned cum = 0;
    if (!ovf) {
        for (int k = 0; k <= 48; k++) { cum += g_hist[k]; if (cum >= KCORR) { kstar = k; break; } }
    }
    if (!ovf && kstar >= 0) {
        g_thres = g_grid[kstar];
        g_need_hist_full = 0; g_need_select_full = 0;
    } else {
        // fallback: need exact full histogram / extended buckets
        g_need_hist_full = 1; g_need_select_full = 1;
        for (int k = 0; k < 64; k++) g_hist[k] = 0;
        g_c49 = 0; g_c50 = 0;
    }
}

// ---------------- fallback: exact full histogram + c49/c50 ----------------
// grid = 2048 blocks, each covers 8 half-rows
__global__ __launch_bounds__(256) void k_fb_hist(const float* __restrict__ sc,
                                                 const float* __restrict__ refw,
                                                 const float* __restrict__ srcw) {
    if (!g_need_hist_full) return;
    __shared__ unsigned h[49];
    __shared__ unsigned sc49, sc50;
    __shared__ float    gs[49];
    if (threadIdx.x < 49) { h[threadIdx.x] = 0; gs[threadIdx.x] = g_grid[threadIdx.x]; }
    if (threadIdx.x == 0) { sc49 = 0; sc50 = 0; }
    __syncthreads();
    float t48 = gs[48], t49 = g_grid[49], t50 = g_grid[50];
    float W48m = g_W48m, W49p = g_W49p, W49m = g_W49m, W50p = g_W50p, W50m = g_W50m;
    int t50pos = g_t50pos;
    unsigned c49 = 0, c50 = 0;
    for (int q = 0; q < 8; q++) {
        int bid2 = blockIdx.x * 8 + q;
        int row = bid2 >> 1, jbase = (bid2 & 1) << 12;
        const float* rp = sc + (size_t)row * NMAT + jbase;
        float r = refw[row], lr = g_logref[row];
        for (int k = 0; k < 16; k++) {
            int jo = threadIdx.x + (k << 8);
            float s = rp[jo];
            float w = s + (lr + g_logsrc[jbase + jo]);
            float v = 0.0f; bool havev = false;
            if (w > W48m) {
                v = expf(s) * (r * srcw[jbase + jo]); havev = true;
                if (v > t48) {
                    int lo = 0, hi = 48;
                    while (lo < hi) { int mid = (lo + hi) >> 1; if (gs[mid] < v) hi = mid; else lo = mid + 1; }
                    atomicAdd(&h[lo], 1u);
                }
            }
            if (w > W49p) c49++;
            else if (w > W49m) {
                if (!havev) { v = expf(s) * (r * srcw[jbase + jo]); havev = true; }
                if (v > t49) c49++;
            }
            if (t50pos) {
                if (w > W50p) c50++;
                else if (w > W50m) {
                    if (!havev) { v = expf(s) * (r * srcw[jbase + jo]); havev = true; }
                    if (v > t50) c50++;
                }
            } else c50++;
        }
    }
    if (c49) atomicAdd(&sc49, c49);
    if (c50) atomicAdd(&sc50, c50);
    __syncthreads();
    if (threadIdx.x < 49 && h[threadIdx.x]) atomicAdd(&g_hist[threadIdx.x], h[threadIdx.x]);
    if (threadIdx.x == 0) {
        if (sc49) atomicAdd(&g_c49, sc49);
        if (sc50) atomicAdd(&g_c50, sc50);
    }
}

__global__ void k_fb_thres() {
    if (blockIdx.x | threadIdx.x) return;
    if (!g_need_hist_full) return;
    unsigned cum = 0; int kstar = -1;
    for (int k = 0; k <= 48; k++) { cum += g_hist[k]; if (cum >= KCORR) { kstar = k; break; } }
    if (kstar < 0) {
        if (g_c49 >= KCORR) kstar = 49;
        else if (g_c50 >= KCORR) kstar = 50;
        else kstar = 51;
    }
    g_thres = g_grid[kstar];
}

// ---------------- fallback: full-matrix select ----------------
__global__ __launch_bounds__(256) void k_fb_select(const float* __restrict__ sc,
                                                   const float* __restrict__ refw,
                                                   const float* __restrict__ srcw) {
    if (!g_need_select_full) return;
    __shared__ float    svv[4096];
    __shared__ int      sii[4096];
    __shared__ unsigned s_cnt, s_base;
    float thr = g_thres;
    float wf = (thr > 0.0f) ? (logf(thr) - MARGIN) : -3.0e38f;
    for (int q = 0; q < 8; q++) {
        if (threadIdx.x == 0) s_cnt = 0;
        __syncthreads();
        int bid2 = blockIdx.x * 8 + q;
        int row = bid2 >> 1, jbase = (bid2 & 1) << 12;
        const float* rp = sc + (size_t)row * NMAT + jbase;
        float r = refw[row], lr = g_logref[row];
        unsigned lane = threadIdx.x & 31u;
        for (int k = 0; k < 16; k++) {
            int jo = threadIdx.x + (k << 8);
            float s = rp[jo];
            float w = s + (lr + g_logsrc[jbase + jo]);
            float v = 0.0f; bool pred = false;
            if (w > wf) { v = expf(s) * (r * srcw[jbase + jo]); pred = (v > thr); }
            unsigned m = __ballot_sync(0xffffffffu, pred);
            if (m) {
                unsigned base;
                int leader = __ffs(m) - 1;
                if ((int)lane == leader) base = atomicAdd(&s_cnt, (unsigned)__popc(m));
                base = __shfl_sync(0xffffffffu, base, leader);
                if (pred) {
                    unsigned slot = base + __popc(m & ((1u << lane) - 1u));
                    svv[slot] = v; sii[slot] = (row << 13) | (jbase + jo);
                }
            }
        }
        __syncthreads();
        unsigned n = s_cnt;
        if (threadIdx.x == 0 && n) s_base = atomicAdd(&g_sel_count, n);
        __syncthreads();
        if (n) {
            unsigned gb = s_base;
            for (unsigned i = threadIdx.x; i < n; i += 256) {
                unsigned slot = gb + i;
                if (slot < CAP2) { g_sel_v[slot] = svv[i]; g_sel_idx[slot] = sii[i]; }
            }
        }
        __syncthreads();
    }
}

// ---------------- primary select from candidate list ----------------
__global__ void k_select() {
    if (g_need_select_full) return;
    unsigned n = g_cand_count; if (n > CAP) n = CAP;
    float thr = g_thres;
    unsigned T = gridDim.x * blockDim.x;
    unsigned lane = threadIdx.x & 31u;
    unsigned gtid = blockIdx.x * blockDim.x + threadIdx.x;
    unsigned wbase = gtid - lane;
    for (unsigned b = wbase; b < n; b += T) {
        unsigned i = b + lane;
        bool pred = false; float v = 0.0f; int idx = 0;
        if (i < n) { v = g_cand_v[i]; idx = g_cand_idx[i]; pred = (v > thr); }
        unsigned m = __ballot_sync(0xffffffffu, pred);
        if (m) {
            unsigned base;
            int leader = __ffs(m) - 1;
            if ((int)lane == leader) base = atomicAdd(&g_sel_count, (unsigned)__popc(m));
            base = __shfl_sync(0xffffffffu, base, leader);
            if (pred) {
                unsigned slot = base + __popc(m & ((1u << lane) - 1u));
                if (slot < CAP2) { g_sel_v[slot] = v; g_sel_idx[slot] = idx; }
            }
        }
    }
}

// ---------------- output init + rank/write ----------------
__global__ void k_init_out(float* __restrict__ out) {
    int t = blockIdx.x * blockDim.x + threadIdx.x;
    if (t < MAXC) {
        out[t]            = -1.0f;
        out[MAXC + t]     = -1.0f;
        out[2 * MAXC + t] = 0.0f;
    }
}

__global__ void k_rank(float* __restrict__ out) {
    unsigned S = g_sel_count; if (S > CAP2) S = CAP2;
    unsigned t = blockIdx.x * blockDim.x + threadIdx.x;
    if (t >= S) return;
    int   my = g_sel_idx[t];
    float v  = g_sel_v[t];
    unsigned rank = 0;
    for (unsigned s = 0; s < S; s++) rank += (g_sel_idx[s] < my);
    if (rank < MAXC) {
        out[rank]            = (float)(my >> 13);
        out[MAXC + rank]     = (float)(my & 8191);
        out[2 * MAXC + rank] = v;
    }
}

// ---------------- launch ----------------
extern "C" void kernel_launch(void* const* d_in, const int* in_sizes, int n_in,
                              void* d_out, int out_size) {
    const float* sc   = (const float*)d_in[0];
    const float* refw = (const float*)d_in[1];
    const float* srcw = (const float*)d_in[2];
    float* out = (float*)d_out;

    k_prep<<<32, 256>>>(refw, srcw);
    k_pass1<<<16384, 256>>>(sc);
    k_finalize<<<256, 256>>>(refw, srcw);
    k_hist<<<128, 256>>>();
    k_thres<<<1, 32>>>();
    k_fb_hist<<<2048, 256>>>(sc, refw, srcw);
    k_fb_thres<<<1, 32>>>();
    k_fb_select<<<2048, 256>>>(sc, refw, srcw);
    k_select<<<128, 256>>>();
    k_init_out<<<32, 256>>>(out);
    k_rank<<<512, 256>>>(out);
}

// round 2
// speedup vs baseline: 1.8173x; 1.8173x over previous
#include <cuda_runtime.h>
#include <math.h>

// ---------------- problem constants ----------------
#define NMAT 8193
#define NI   8192
#define TFLAT 67117056u          // 8192 * 8193 (rows 0..8191 incl. dustbin col)
#define KCORR 2048u
#define MAXC 8192
#define NGRID 52
#define CAP  (1u << 21)          // primary candidate buffer (2M entries)
#define CAP2 (1u << 17)          // selected buffer
#define BLK_ELEMS 16384u
#define NBLK 4097                // ceil(TFLAT / BLK_ELEMS)
#define STAGE 2048               // per-block candidate staging

// ---------------- device scratch ----------------
__device__ float    g_cand_v[CAP];
__device__ int      g_cand_idx[CAP];
__device__ float    g_sel_v[CAP2];
__device__ int      g_sel_idx[CAP2];
__device__ float    g_lr[NI + 1];      // log(ref), lr[8192] = -1e30 (row sentinel)
__device__ float    g_ls[NI + 1];      // log(src), ls[8192] = -1e30 (dustbin col)
__device__ unsigned g_cand_count;
__device__ unsigned g_cand_overflow;
__device__ unsigned g_sel_count;
__device__ unsigned g_c49, g_c50;
__device__ unsigned g_hist[64];
__device__ float    g_grid[NGRID];
__device__ float    g_wcap;            // log(grid[44]) - margin : capture cutoff
__device__ float    g_thres;
__device__ float    g_W48m, g_W49p, g_W49m, g_W50p, g_W50m;
__device__ int      g_t50pos;
__device__ int      g_need_hist_full;
__device__ int      g_need_select_full;

// ---------------- prep: logs, grid, resets ----------------
__global__ void k_prep(const float* __restrict__ refw, const float* __restrict__ srcw) {
    int gid = blockIdx.x * blockDim.x + threadIdx.x;
    if (gid < NI) {
        g_lr[gid] = logf(refw[gid]);
        g_ls[gid] = logf(srcw[gid]);
    }
    if (gid == NI) { g_lr[NI] = -1e30f; g_ls[NI] = -1e30f; }
    if (gid < 64) g_hist[gid] = 0;
    if (gid == 0) {
        g_cand_count = 0; g_cand_overflow = 0; g_sel_count = 0;
        g_c49 = 0; g_c50 = 0;
        g_need_hist_full = 0; g_need_select_full = 0;
        float t = 0.5f;
        for (int k = 0; k < NGRID; k++) { g_grid[k] = t; t -= 0.01f; }
        g_wcap = logf(g_grid[44]) - 0.02f;   // capture everything with v > ~0.0588
        float t48 = g_grid[48], t49 = g_grid[49], t50 = g_grid[50];
        g_W48m = logf(t48) - 0.005f;
        g_W49p = logf(t49) + 0.005f;
        g_W49m = logf(t49) - 0.005f;
        if (t50 > 0.0f) {
            g_t50pos = 1;
            g_W50p = logf(t50) + 0.005f;
            g_W50m = logf(t50) - 0.005f;
        } else { g_t50pos = 0; g_W50p = 0.0f; g_W50m = 0.0f; }
    }
}

// ---------------- main pass: flat float4 scan + hierarchical max prune ----------------
__global__ __launch_bounds__(256) void k_pass1(const float* __restrict__ sc,
                                               const float* __restrict__ refw,
                                               const float* __restrict__ srcw) {
    __shared__ float    sv[STAGE];
    __shared__ int      si[STAGE];
    __shared__ unsigned s_cnt, s_base;
    __shared__ float    s_cthr, s_wcap, s_lr0, s_lr1, s_lr2;
    __shared__ unsigned s_b1, s_b2;
    __shared__ int      s_r0;

    unsigned tid = threadIdx.x;
    if (tid == 0) {
        s_cnt = 0;
        unsigned start = blockIdx.x * BLK_ELEMS;
        int r0 = (int)(start / 8193u);
        unsigned b1 = (unsigned)(r0 + 1) * 8193u;
        unsigned b2 = b1 + 8193u;
        float lr0 = g_lr[r0];
        float lr1 = g_lr[r0 + 1];
        float lr2 = g_lr[r0 + 2 <= NI ? r0 + 2 : NI];
        float wcap = g_wcap;
        s_r0 = r0; s_b1 = b1; s_b2 = b2;
        s_lr0 = lr0; s_lr1 = lr1; s_lr2 = lr2;
        s_wcap = wcap;
        s_cthr = wcap - fmaxf(lr0, fmaxf(lr1, lr2)) - 1e-3f;
    }
    __syncthreads();
    const float cthr = s_cthr, wcap = s_wcap;
    const float lr0 = s_lr0, lr1 = s_lr1, lr2 = s_lr2;
    const int r0 = s_r0;
    const unsigned b1 = s_b1, b2 = s_b2;
    const unsigned start = blockIdx.x * BLK_ELEMS;
    const float4* __restrict__ p4 = (const float4*)sc;

#pragma unroll
    for (int k = 0; k < 4; k++) {
        unsigned e0 = start + (unsigned)k * 4096u + tid * 16u;
        unsigned q = e0 >> 2;
        float4 d0 = p4[q + 0];
        float4 d1 = p4[q + 1];
        float4 d2 = p4[q + 2];
        float4 d3 = p4[q + 3];
        float m0 = fmaxf(fmaxf(d0.x, d0.y), fmaxf(d0.z, d0.w));
        float m1 = fmaxf(fmaxf(d1.x, d1.y), fmaxf(d1.z, d1.w));
        float m2 = fmaxf(fmaxf(d2.x, d2.y), fmaxf(d2.z, d2.w));
        float m3 = fmaxf(fmaxf(d3.x, d3.y), fmaxf(d3.z, d3.w));
        float mm = fmaxf(fmaxf(m0, m1), fmaxf(m2, m3));
        if (mm > cthr) {
#pragma unroll
            for (int qq = 0; qq < 4; qq++) {
                float mq = (qq == 0) ? m0 : (qq == 1) ? m1 : (qq == 2) ? m2 : m3;
                if (mq > cthr) {
                    float4 d = (qq == 0) ? d0 : (qq == 1) ? d1 : (qq == 2) ? d2 : d3;
                    unsigned eq = e0 + (unsigned)qq * 4u;
#pragma unroll
                    for (int ii = 0; ii < 4; ii++) {
                        float s = (ii == 0) ? d.x : (ii == 1) ? d.y : (ii == 2) ? d.z : d.w;
                        unsigned e = eq + (unsigned)ii;
                        int ge1 = (e >= b1), ge2 = (e >= b2);
                        int r = r0 + ge1 + ge2;
                        float lr = ge2 ? lr2 : (ge1 ? lr1 : lr0);
                        unsigned c = e - (unsigned)r * 8193u;
                        float w = s + (lr + g_ls[c]);
                        if (w > wcap) {
                            float v = expf(s) * (refw[r] * srcw[c]);
                            unsigned slot = atomicAdd(&s_cnt, 1u);
                            if (slot < (unsigned)STAGE) {
                                sv[slot] = v;
                                si[slot] = (r << 13) | (int)c;
                            }
                        }
                    }
                }
            }
        }
    }
    __syncthreads();
    unsigned n = s_cnt;
    unsigned nc = n < (unsigned)STAGE ? n : (unsigned)STAGE;
    if (tid == 0) {
        if (n > (unsigned)STAGE) atomicExch(&g_cand_overflow, 1u);
        if (nc) s_base = atomicAdd(&g_cand_count, nc);
    }
    __syncthreads();
    if (!nc) return;
    unsigned gb = s_base;
    for (unsigned i = tid; i < nc; i += 256u) {
        unsigned slot = gb + i;
        if (slot < CAP) {
            g_cand_v[slot]   = sv[i];
            g_cand_idx[slot] = si[i];
        }
    }
}

// ---------------- histogram over candidates (buckets 0..48, trust 0..44) ----------------
__global__ void k_hist() {
    __shared__ unsigned h[49];
    __shared__ float    gs[49];
    if (threadIdx.x < 49) { h[threadIdx.x] = 0; gs[threadIdx.x] = g_grid[threadIdx.x]; }
    __syncthreads();
    unsigned n = g_cand_count; if (n > CAP) n = CAP;
    float t48 = gs[48];
    unsigned T = gridDim.x * blockDim.x;
    for (unsigned i = blockIdx.x * blockDim.x + threadIdx.x; i < n; i += T) {
        float v = g_cand_v[i];
        if (v > t48) {
            int lo = 0, hi = 48;
            while (lo < hi) { int mid = (lo + hi) >> 1; if (gs[mid] < v) hi = mid; else lo = mid + 1; }
            atomicAdd(&h[lo], 1u);
        }
    }
    __syncthreads();
    if (threadIdx.x < 49 && h[threadIdx.x]) atomicAdd(&g_hist[threadIdx.x], h[threadIdx.x]);
}

// ---------------- threshold (primary) ----------------
__global__ void k_thres() {
    if (blockIdx.x | threadIdx.x) return;
    bool bad = (g_cand_overflow != 0u) || (g_cand_count > CAP);
    int kstar = -1; unsigned cum = 0;
    if (!bad) {
        for (int k = 0; k <= 44; k++) { cum += g_hist[k]; if (cum >= KCORR) { kstar = k; break; } }
    }
    if (!bad && kstar >= 0) {
        g_thres = g_grid[kstar];
        g_need_hist_full = 0; g_need_select_full = 0;
    } else {
        g_need_hist_full = 1; g_need_select_full = 1;
        for (int k = 0; k < 64; k++) g_hist[k] = 0;
        g_c49 = 0; g_c50 = 0;
    }
}

// ---------------- fallback: exact full histogram + c49/c50 (predicated off) ----------------
__global__ __launch_bounds__(256) void k_fb_hist(const float* __restrict__ sc,
                                                 const float* __restrict__ refw,
                                                 const float* __restrict__ srcw) {
    if (!g_need_hist_full) return;
    __shared__ unsigned h[49];
    __shared__ unsigned sc49, sc50;
    __shared__ float    gs[49];
    if (threadIdx.x < 49) { h[threadIdx.x] = 0; gs[threadIdx.x] = g_grid[threadIdx.x]; }
    if (threadIdx.x == 0) { sc49 = 0; sc50 = 0; }
    __syncthreads();
    float t48 = gs[48], t49 = g_grid[49], t50 = g_grid[50];
    float W48m = g_W48m, W49p = g_W49p, W49m = g_W49m, W50p = g_W50p, W50m = g_W50m;
    int t50pos = g_t50pos;
    unsigned c49 = 0, c50 = 0;
    for (int q = 0; q < 8; q++) {
        int bid2 = blockIdx.x * 8 + q;
        int row = bid2 >> 1, jbase = (bid2 & 1) << 12;
        const float* rp = sc + (size_t)row * NMAT + jbase;
        float r = refw[row], lr = g_lr[row];
        for (int k = 0; k < 16; k++) {
            int jo = threadIdx.x + (k << 8);
            float s = rp[jo];
            float w = s + (lr + g_ls[jbase + jo]);
            float v = 0.0f; bool havev = false;
            if (w > W48m) {
                v = expf(s) * (r * srcw[jbase + jo]); havev = true;
                if (v > t48) {
                    int lo = 0, hi = 48;
                    while (lo < hi) { int mid = (lo + hi) >> 1; if (gs[mid] < v) hi = mid; else lo = mid + 1; }
                    atomicAdd(&h[lo], 1u);
                }
            }
            if (w > W49p) c49++;
            else if (w > W49m) {
                if (!havev) { v = expf(s) * (r * srcw[jbase + jo]); havev = true; }
                if (v > t49) c49++;
            }
            if (t50pos) {
                if (w > W50p) c50++;
                else if (w > W50m) {
                    if (!havev) { v = expf(s) * (r * srcw[jbase + jo]); havev = true; }
                    if (v > t50) c50++;
                }
            } else c50++;
        }
    }
    if (c49) atomicAdd(&sc49, c49);
    if (c50) atomicAdd(&sc50, c50);
    __syncthreads();
    if (threadIdx.x < 49 && h[threadIdx.x]) atomicAdd(&g_hist[threadIdx.x], h[threadIdx.x]);
    if (threadIdx.x == 0) {
        if (sc49) atomicAdd(&g_c49, sc49);
        if (sc50) atomicAdd(&g_c50, sc50);
    }
}

__global__ void k_fb_thres() {
    if (blockIdx.x | threadIdx.x) return;
    if (!g_need_hist_full) return;
    unsigned cum = 0; int kstar = -1;
    for (int k = 0; k <= 48; k++) { cum += g_hist[k]; if (cum >= KCORR) { kstar = k; break; } }
    if (kstar < 0) {
        if (g_c49 >= KCORR) kstar = 49;
        else if (g_c50 >= KCORR) kstar = 50;
        else kstar = 51;
    }
    g_thres = g_grid[kstar];
}

// ---------------- fallback: full-matrix select (predicated off) ----------------
__global__ __launch_bounds__(256) void k_fb_select(const float* __restrict__ sc,
                                                   const float* __restrict__ refw,
                                                   const float* __restrict__ srcw) {
    if (!g_need_select_full) return;
    __shared__ float    svv[4096];
    __shared__ int      sii[4096];
    __shared__ unsigned s_cnt, s_base;
    float thr = g_thres;
    float wf = (thr > 0.0f) ? (logf(thr) - 0.005f) : -3.0e38f;
    for (int q = 0; q < 8; q++) {
        if (threadIdx.x == 0) s_cnt = 0;
        __syncthreads();
        int bid2 = blockIdx.x * 8 + q;
        int row = bid2 >> 1, jbase = (bid2 & 1) << 12;
        const float* rp = sc + (size_t)row * NMAT + jbase;
        float r = refw[row], lr = g_lr[row];
        unsigned lane = threadIdx.x & 31u;
        for (int k = 0; k < 16; k++) {
            int jo = threadIdx.x + (k << 8);
            float s = rp[jo];
            float w = s + (lr + g_ls[jbase + jo]);
            float v = 0.0f; bool pred = false;
            if (w > wf) { v = expf(s) * (r * srcw[jbase + jo]); pred = (v > thr); }
            unsigned m = __ballot_sync(0xffffffffu, pred);
            if (m) {
                unsigned base;
                int leader = __ffs(m) - 1;
                if ((int)lane == leader) base = atomicAdd(&s_cnt, (unsigned)__popc(m));
                base = __shfl_sync(0xffffffffu, base, leader);
                if (pred) {
                    unsigned slot = base + __popc(m & ((1u << lane) - 1u));
                    svv[slot] = v; sii[slot] = (row << 13) | (jbase + jo);
                }
            }
        }
        __syncthreads();
        unsigned n = s_cnt;
        if (threadIdx.x == 0 && n) s_base = atomicAdd(&g_sel_count, n);
        __syncthreads();
        if (n) {
            unsigned gb = s_base;
            for (unsigned i = threadIdx.x; i < n; i += 256) {
                unsigned slot = gb + i;
                if (slot < CAP2) { g_sel_v[slot] = svv[i]; g_sel_idx[slot] = sii[i]; }
            }
        }
        __syncthreads();
    }
}

// ---------------- primary select (from candidates) + output init ----------------
__global__ void k_select(float* __restrict__ out) {
    unsigned gtid = blockIdx.x * blockDim.x + threadIdx.x;
    if (gtid < 3u * MAXC) out[gtid] = (gtid < 2u * MAXC) ? -1.0f : 0.0f;
    if (g_need_select_full) return;
    unsigned n = g_cand_count; if (n > CAP) n = CAP;
    float thr = g_thres;
    unsigned T = gridDim.x * blockDim.x;
    unsigned lane = threadIdx.x & 31u;
    unsigned wbase = gtid - lane;
    for (unsigned b = wbase; b < n; b += T) {
        unsigned i = b + lane;
        bool pred = false; float v = 0.0f; int idx = 0;
        if (i < n) { v = g_cand_v[i]; idx = g_cand_idx[i]; pred = (v > thr); }
        unsigned m = __ballot_sync(0xffffffffu, pred);
        if (m) {
            unsigned base;
            int leader = __ffs(m) - 1;
            if ((int)lane == leader) base = atomicAdd(&g_sel_count, (unsigned)__popc(m));
            base = __shfl_sync(0xffffffffu, base, leader);
            if (pred) {
                unsigned slot = base + __popc(m & ((1u << lane) - 1u));
                if (slot < CAP2) { g_sel_v[slot] = v; g_sel_idx[slot] = idx; }
            }
        }
    }
}

// ---------------- rank (row-major order) + write ----------------
__global__ __launch_bounds__(256) void k_rank(float* __restrict__ out) {
    __shared__ int tile[1024];
    unsigned S = g_sel_count; if (S > CAP2) S = CAP2;
    unsigned t = blockIdx.x * blockDim.x + threadIdx.x;
    if (blockIdx.x * blockDim.x >= S) return;
    bool act = (t < S);
    int   my = 0; float v = 0.0f;
    if (act) { my = g_sel_idx[t]; v = g_sel_v[t]; }
    unsigned rank = 0;
    for (unsigned base = 0; base < S; base += 1024u) {
        unsigned n = S - base; if (n > 1024u) n = 1024u;
        __syncthreads();
        for (unsigned i = threadIdx.x; i < n; i += 256u) tile[i] = g_sel_idx[base + i];
        __syncthreads();
        if (act) {
            unsigned i = 0;
            for (; i + 4 <= n; i += 4) {
                rank += (tile[i] < my) + (tile[i+1] < my) + (tile[i+2] < my) + (tile[i+3] < my);
            }
            for (; i < n; i++) rank += (tile[i] < my);
        }
    }
    if (act && rank < MAXC) {
        out[rank]            = (float)(my >> 13);
        out[MAXC + rank]     = (float)(my & 8191);
        out[2 * MAXC + rank] = v;
    }
}

// ---------------- launch ----------------
extern "C" void kernel_launch(void* const* d_in, const int* in_sizes, int n_in,
                              void* d_out, int out_size) {
    const float* sc   = (const float*)d_in[0];
    const float* refw = (const float*)d_in[1];
    const float* srcw = (const float*)d_in[2];
    float* out = (float*)d_out;

    k_prep<<<64, 256>>>(refw, srcw);
    k_pass1<<<NBLK, 256>>>(sc, refw, srcw);
    k_hist<<<148, 256>>>();
    k_thres<<<1, 32>>>();
    k_fb_hist<<<2048, 256>>>(sc, refw, srcw);
    k_fb_thres<<<1, 32>>>();
    k_fb_select<<<2048, 256>>>(sc, refw, srcw);
    k_select<<<148, 256>>>(out);
    k_rank<<<512, 256>>>(out);
}